// round 17
// baseline (speedup 1.0000x reference)
#include <cuda_runtime.h>
#include <cuda_bf16.h>
#include <math.h>
#include <stdint.h>

#define B_ 2048
#define F_ 512
#define H_ 256
#define E_ 64
#define K_ 8
#define PITCH 48   // smem row pitch in bf16 (96 B, 16B-aligned every row)

// ------------------------- device scratch (no allocs allowed) ---------------
__device__ float g_M[F_ * E_];
__device__ float g_c[E_];
__device__ float g_enT[F_ * E_];
__device__ float g_t[E_];
__device__ float g_score[B_ * E_];
__device__ float g_w[B_ * K_];
__device__ int   g_cnt[E_];
__device__ int   g_list[E_ * B_];
__device__ float g_partial[(size_t)B_ * K_ * F_];            // 32 MB
__device__ __nv_bfloat16 g_xh[B_ * F_];
__device__ __nv_bfloat16 g_xl[B_ * F_];
__device__ __nv_bfloat16 g_WhT[(size_t)E_ * F_ * F_];        // [e][g][f] K-major
__device__ __nv_bfloat16 g_WlT[(size_t)E_ * F_ * F_];

// mma.m16n8k16 row.col f32 <- bf16 x bf16 (baseline PTX, ok on sm_103)
#define MMA16816(c, a0, a1, a2, a3, b0, b1)                                    \
    asm volatile(                                                              \
        "mma.sync.aligned.m16n8k16.row.col.f32.bf16.bf16.f32 "                 \
        "{%0,%1,%2,%3}, {%4,%5,%6,%7}, {%8,%9}, {%0,%1,%2,%3};"                \
        : "+f"((c)[0]), "+f"((c)[1]), "+f"((c)[2]), "+f"((c)[3])               \
        : "r"(a0), "r"(a1), "r"(a2), "r"(a3), "r"(b0), "r"(b1))

// ------------------------- prologue: expert-side precompute ------------------
__global__ void prep_expert_kernel(const float* __restrict__ ef,
                                   const float* __restrict__ trust,
                                   const float* __restrict__ dt,
                                   const float* __restrict__ proj_b,
                                   const float* __restrict__ emb) {
    int e = blockIdx.x;
    int t = threadIdx.x;  // 128
    __shared__ float red[128];

    float s = 0.f;
    for (int f = t; f < F_; f += 128) { float v = ef[e * F_ + f]; s += v * v; }
    red[t] = s; __syncthreads();
    for (int o = 64; o > 0; o >>= 1) { if (t < o) red[t] += red[t + o]; __syncthreads(); }
    float denom = fmaxf(sqrtf(red[0]), 1e-8f);
    for (int f = t; f < F_; f += 128) g_enT[f * E_ + e] = ef[e * F_ + f] / denom;

    float s2 = 0.f;
    for (int h = t; h < H_; h += 128) s2 += proj_b[h] * emb[e * H_ + h];
    __syncthreads(); red[t] = s2; __syncthreads();
    for (int o = 64; o > 0; o >>= 1) { if (t < o) red[t] += red[t + o]; __syncthreads(); }
    if (t == 0) {
        g_c[e] = red[0] * 0.0625f;
        g_t[e] = trust[e] * fmaxf(0.1f, expf(-0.005f * dt[e]));
        g_cnt[e] = 0;
    }
}

// M[f][e] = sum_h proj_w[h][f] * emb[e][h] / 16
__global__ void prep_M_kernel(const float* __restrict__ pw,
                              const float* __restrict__ emb) {
    int t = threadIdx.x;          // 256
    int fi = t >> 6;
    int e = t & 63;
    int fbase = blockIdx.x * 4;
    __shared__ float sPw[64][4];
    float acc = 0.f;
    for (int h0 = 0; h0 < H_; h0 += 64) {
        __syncthreads();
        sPw[t >> 2][t & 3] = pw[(h0 + (t >> 2)) * F_ + fbase + (t & 3)];
        __syncthreads();
        #pragma unroll 8
        for (int hl = 0; hl < 64; hl++)
            acc += sPw[hl][fi] * emb[e * H_ + h0 + hl];
    }
    g_M[(fbase + fi) * E_ + e] = acc * 0.0625f;
}

// ------------------------- bf16 split conversions ----------------------------
__global__ void xsplit_kernel(const float* __restrict__ feat) {
    int i = blockIdx.x * 256 + threadIdx.x;   // over B*F = 1M
    float v = feat[i];
    __nv_bfloat16 hi = __float2bfloat16(v);
    g_xh[i] = hi;
    g_xl[i] = __float2bfloat16(v - __bfloat162float(hi));
}

// Transpose+split: WhT[e][g][f] = bf16_hi(W[e][f][g]), WlT = residual.
__global__ void wsplit_kernel(const float* __restrict__ fw) {
    __shared__ float tile[32][33];
    int e = blockIdx.z, f0 = blockIdx.y * 32, g0 = blockIdx.x * 32;
    int tx = threadIdx.x & 31, ty = threadIdx.x >> 5;  // ty 0..7
    const float* src = fw + ((size_t)e * F_ + f0) * F_ + g0;
    #pragma unroll
    for (int r = 0; r < 4; r++)
        tile[ty + r * 8][tx] = src[(size_t)(ty + r * 8) * F_ + tx];
    __syncthreads();
    size_t dstbase = ((size_t)e * F_ + g0) * F_ + f0;
    #pragma unroll
    for (int r = 0; r < 4; r++) {
        float v = tile[tx][ty + r * 8];
        __nv_bfloat16 hi = __float2bfloat16(v);
        g_WhT[dstbase + (size_t)(ty + r * 8) * F_ + tx] = hi;
        g_WlT[dstbase + (size_t)(ty + r * 8) * F_ + tx] =
            __float2bfloat16(v - __bfloat162float(hi));
    }
}

// ------------------------- scores: gate * sim * t ----------------------------
__global__ void __launch_bounds__(256) score_kernel(const float* __restrict__ feat) {
    int b0 = blockIdx.x * 16;
    __shared__ float sx[16][F_];
    __shared__ float snorm[16];
    int t = threadIdx.x;

    for (int i = t; i < 16 * F_ / 4; i += 256)
        *(float4*)&sx[i >> 7][(i & 127) << 2] =
            *(const float4*)&feat[(size_t)(b0 + (i >> 7)) * F_ + ((i & 127) << 2)];
    __syncthreads();

    int warp = t >> 5, lane = t & 31;
    for (int rr = 0; rr < 2; rr++) {
        int r = warp * 2 + rr;
        float s = 0.f;
        for (int f = lane; f < F_; f += 32) { float v = sx[r][f]; s += v * v; }
        for (int o = 16; o; o >>= 1) s += __shfl_xor_sync(0xffffffffu, s, o);
        if (lane == 0) snorm[r] = sqrtf(s);
    }
    __syncthreads();

    int r = t >> 4;
    int el = t & 15;
    float inv = 1.0f / fmaxf(snorm[r], 1e-8f);
    const float4* M4 = (const float4*)g_M;
    const float4* E4 = (const float4*)g_enT;
    float4 s1 = {0, 0, 0, 0}, s2 = {0, 0, 0, 0};
    #pragma unroll 4
    for (int f = 0; f < F_; f++) {
        float x = sx[r][f];
        float4 m = M4[f * 16 + el];
        float4 en = E4[f * 16 + el];
        s1.x += x * m.x;  s1.y += x * m.y;  s1.z += x * m.z;  s1.w += x * m.w;
        s2.x += x * en.x; s2.y += x * en.y; s2.z += x * en.z; s2.w += x * en.w;
    }
    float sv1[4] = {s1.x, s1.y, s1.z, s1.w};
    float sv2[4] = {s2.x, s2.y, s2.z, s2.w};
    #pragma unroll
    for (int j = 0; j < 4; j++) {
        int e = 4 * el + j;
        float gate = 1.0f / (1.0f + expf(-(sv1[j] + g_c[e])));
        float sim = fmaxf(sv2[j], 0.0f) * inv;
        g_score[(size_t)(b0 + r) * E_ + e] = gate * sim * g_t[e];
    }
}

// ------------------------- top-8 + softmax + bucket --------------------------
__global__ void topk_kernel() {
    int warp = threadIdx.x >> 5, lane = threadIdx.x & 31;
    int b = blockIdx.x * 8 + warp;
    float v0 = g_score[b * E_ + lane];
    float v1 = g_score[b * E_ + 32 + lane];

    float selv[K_]; int seli[K_];
    #pragma unroll
    for (int k = 0; k < K_; k++) {
        float bv; int bi;
        if (v0 >= v1) { bv = v0; bi = lane; } else { bv = v1; bi = lane + 32; }
        for (int o = 16; o; o >>= 1) {
            float ov = __shfl_xor_sync(0xffffffffu, bv, o);
            int oi = __shfl_xor_sync(0xffffffffu, bi, o);
            if (ov > bv || (ov == bv && oi < bi)) { bv = ov; bi = oi; }
        }
        selv[k] = bv; seli[k] = bi;
        if (bi == lane) v0 = -1.0f;
        else if (bi == lane + 32) v1 = -1.0f;
    }
    float m = selv[0];
    float ex[K_], sum = 0.f;
    #pragma unroll
    for (int k = 0; k < K_; k++) { ex[k] = expf(selv[k] - m); sum += ex[k]; }
    float rs = 1.0f / sum;
    if (lane < K_) {
        int k = lane;
        int entry = b * K_ + k;
        g_w[entry] = ex[k] * rs;
        int e = seli[k];
        int pos = atomicAdd(&g_cnt[e], 1);
        g_list[e * B_ + pos] = entry;
    }
}

// ------------------------- grouped expert GEMM: HMMA bf16 --------------------
// CTA tile: 128 gathered rows x 64 cols, 8 warps (warp tile 32x32).
// K = 3 segments x 512 bf16 (xh*Wh + xl*Wh + xh*Wl), fp32 acc in registers.
// A and B both K-major in smem, pitch 48 bf16 (96B: 16B-aligned rows).
__global__ void __launch_bounds__(256) tgemm_kernel(const float* __restrict__ fb) {
    __shared__ __nv_bfloat16 sA[2][128][PITCH];   // [buf][m][k]
    __shared__ __nv_bfloat16 sB[2][64][PITCH];    // [buf][n][k]
    __shared__ int sEntry[128];

    int e = blockIdx.z;
    int ne = g_cnt[e];
    int m0 = blockIdx.x * 128;
    if (m0 >= ne) return;
    int n0 = blockIdx.y * 64;

    int t = threadIdx.x;
    int lane = t & 31, wid = t >> 5;
    int wm = wid >> 1, wn = wid & 1;       // 4 x 2 warp grid

    if (t < 128) sEntry[t] = (m0 + t < ne) ? g_list[e * B_ + m0 + t] : -1;
    __syncthreads();

    // A loader: 2 uint4 per thread. idx = t + 256*i -> m = idx>>2, kq = idx&3
    int am[2], akq[2];
    size_t arow[2];
    #pragma unroll
    for (int i = 0; i < 2; i++) {
        int idx = t + 256 * i;
        am[i] = idx >> 2; akq[i] = idx & 3;
        int entry = sEntry[am[i]];
        arow[i] = (size_t)(entry >= 0 ? (entry >> 3) : 0) * F_ + akq[i] * 8;
    }
    // B loader: 1 uint4 per thread. n = t>>2, kq = t&3
    int bn = t >> 2, bkq = t & 3;
    size_t brow = ((size_t)e * F_ + n0 + bn) * F_ + bkq * 8;

    // chunk c: seg = c>>4, k0 = (c&15)*32
    // preload chunk 0 -> buf 0
    #pragma unroll
    for (int i = 0; i < 2; i++)
        *(uint4*)&sA[0][am[i]][akq[i] * 8] = *(const uint4*)(g_xh + arow[i]);
    *(uint4*)&sB[0][bn][bkq * 8] = *(const uint4*)(g_WhT + brow);
    __syncthreads();

    float acc[2][4][4] = {};
    int r4 = lane >> 2, q4 = lane & 3;
    int buf = 0;
    #pragma unroll 1
    for (int c = 0; c < 48; c++) {
        uint4 pa[2], pb;
        bool has_next = (c + 1) < 48;
        if (has_next) {
            int cn = c + 1;
            int seg = cn >> 4;
            int k0 = (cn & 15) << 5;
            const __nv_bfloat16* A = (seg == 1) ? g_xl : g_xh;
            const __nv_bfloat16* Bw = (seg == 2) ? g_WlT : g_WhT;
            pa[0] = *(const uint4*)(A + arow[0] + k0);
            pa[1] = *(const uint4*)(A + arow[1] + k0);
            pb = *(const uint4*)(Bw + brow + k0);
        }
        // 2 k-steps of 16 over this chunk
        #pragma unroll
        for (int ks = 0; ks < 2; ks++) {
            uint32_t afr[2][4];
            #pragma unroll
            for (int mt = 0; mt < 2; mt++) {
                const __nv_bfloat16* base =
                    &sA[buf][wm * 32 + mt * 16 + r4][ks * 16 + q4 * 2];
                afr[mt][0] = *(const uint32_t*)(base);
                afr[mt][1] = *(const uint32_t*)(base + 8 * PITCH);
                afr[mt][2] = *(const uint32_t*)(base + 8);
                afr[mt][3] = *(const uint32_t*)(base + 8 * PITCH + 8);
            }
            #pragma unroll
            for (int nt = 0; nt < 4; nt++) {
                const __nv_bfloat16* bbase =
                    &sB[buf][wn * 32 + nt * 8 + r4][ks * 16 + q4 * 2];
                uint32_t b0 = *(const uint32_t*)(bbase);
                uint32_t b1 = *(const uint32_t*)(bbase + 8);
                #pragma unroll
                for (int mt = 0; mt < 2; mt++)
                    MMA16816(acc[mt][nt], afr[mt][0], afr[mt][1], afr[mt][2],
                             afr[mt][3], b0, b1);
            }
        }
        if (has_next) {
            int nb = buf ^ 1;
            *(uint4*)&sA[nb][am[0]][akq[0] * 8] = pa[0];
            *(uint4*)&sA[nb][am[1]][akq[1] * 8] = pa[1];
            *(uint4*)&sB[nb][bn][bkq * 8] = pb;
            __syncthreads();
            buf = nb;
        }
    }

    // Epilogue: acc[mt][nt] regs c0..c3:
    //  c0:(r, col) c1:(r, col+1) c2:(r+8, col) c3:(r+8, col+1)
    //  r = wm*32 + mt*16 + r4, col = n0 + wn*32 + nt*8 + q4*2
    #pragma unroll
    for (int mt = 0; mt < 2; mt++) {
        int mrow0 = wm * 32 + mt * 16 + r4;
        int e0 = sEntry[mrow0];
        int e1 = sEntry[mrow0 + 8];
        float w0 = (e0 >= 0) ? g_w[e0] : 0.f;
        float w1 = (e1 >= 0) ? g_w[e1] : 0.f;
        #pragma unroll
        for (int nt = 0; nt < 4; nt++) {
            int col = n0 + wn * 32 + nt * 8 + q4 * 2;
            float2 bias = *(const float2*)(fb + (size_t)e * F_ + col);
            if (e0 >= 0) {
                float2 o = {w0 * (acc[mt][nt][0] + bias.x),
                            w0 * (acc[mt][nt][1] + bias.y)};
                *(float2*)(g_partial + (size_t)e0 * F_ + col) = o;
            }
            if (e1 >= 0) {
                float2 o = {w1 * (acc[mt][nt][2] + bias.x),
                            w1 * (acc[mt][nt][3] + bias.y)};
                *(float2*)(g_partial + (size_t)e1 * F_ + col) = o;
            }
        }
    }
}

// ------------------------- final reduce over K slots -------------------------
__global__ void reduce_kernel(float4* __restrict__ out) {
    int i = blockIdx.x * 256 + threadIdx.x;
    const float4* p = (const float4*)g_partial;
    int b = i >> 7;
    int f4 = i & 127;
    float4 s = {0.f, 0.f, 0.f, 0.f};
    #pragma unroll
    for (int k = 0; k < K_; k++) {
        float4 v = p[(size_t)(b * K_ + k) * 128 + f4];
        s.x += v.x; s.y += v.y; s.z += v.z; s.w += v.w;
    }
    out[i] = s;
}

// ------------------------- launch ------------------------------------------
extern "C" void kernel_launch(void* const* d_in, const int* in_sizes, int n_in,
                              void* d_out, int out_size) {
    const float* features  = (const float*)d_in[0];
    const float* proj_w    = (const float*)d_in[1];
    const float* proj_b    = (const float*)d_in[2];
    const float* emb       = (const float*)d_in[3];
    const float* ef        = (const float*)d_in[4];
    const float* trust     = (const float*)d_in[5];
    const float* dt        = (const float*)d_in[6];
    const float* fst_w     = (const float*)d_in[7];
    const float* fst_b     = (const float*)d_in[8];
    float* out = (float*)d_out;

    prep_expert_kernel<<<E_, 128>>>(ef, trust, dt, proj_b, emb);
    prep_M_kernel<<<F_ / 4, 256>>>(proj_w, emb);
    xsplit_kernel<<<B_ * F_ / 256, 256>>>(features);
    wsplit_kernel<<<dim3(16, 16, E_), 256>>>(fst_w);
    score_kernel<<<B_ / 16, 256>>>(features);
    topk_kernel<<<B_ / 8, 256>>>();
    tgemm_kernel<<<dim3(B_ / 128, F_ / 64, E_), 256>>>(fst_b);
    reduce_kernel<<<(B_ * F_ / 4) / 256, 256>>>((float4*)out);
}